// round 12
// baseline (speedup 1.0000x reference)
#include <cuda_runtime.h>
#include <cstdint>

#define Nn 62
#define Mm 512
#define Dd 256
#define D4 (Dd / 4)
#define BM 64
#define BN 256
#define BK 32
#define BSTR 258
#define NCHUNK (Dd / BK)
#define MARGIN_F 0.2f

__device__ float g_sq[Nn * Mm];
__device__ float g_hard[Nn * (Mm / BM)];
__device__ float g_dist[Nn * (Mm / BM)];

__device__ __forceinline__ void fma2(unsigned long long& c,
                                     unsigned long long a,
                                     unsigned long long b) {
    asm("fma.rn.f32x2 %0, %1, %2, %0;" : "+l"(c) : "l"(a), "l"(b));
}

// ---------------- squared row norms: one warp per row ----------------
__global__ void sq_kernel(const float* __restrict__ f) {
    int row  = blockIdx.x * 8 + (threadIdx.x >> 5);
    int lane = threadIdx.x & 31;
    const float4* f4 = (const float4*)f + (size_t)row * D4;
    float4 v0 = f4[lane];
    float4 v1 = f4[lane + 32];
    float s = v0.x * v0.x + v0.y * v0.y + v0.z * v0.z + v0.w * v0.w
            + v1.x * v1.x + v1.y * v1.y + v1.z * v1.z + v1.w * v1.w;
#pragma unroll
    for (int o = 16; o; o >>= 1) s += __shfl_xor_sync(0xffffffffu, s, o);
    if (lane == 0) g_sq[row] = s;
}

// ---- main: gram GEMM (f32x2) + dist + hard pos/neg per 64-row tile ----
__global__ void __launch_bounds__(256, 1)
triplet_kernel(const float* __restrict__ feature) {
    extern __shared__ float smem[];
    float* As = smem;                  // BM*Dd*2 floats, duplicated {a,a}
    float* Bs = smem + BM * Dd * 2;    // BK*BSTR floats, transposed [k][j]

    const int tid = threadIdx.x;
    const int it  = tid >> 5;          // warp id: rows it+8r
    const int jt  = tid & 31;          // lane: cols 2*jt+64p (+0/1)
    const int n   = blockIdx.y;
    const int i0  = blockIdx.x * BM;
    const float4* f4 = (const float4*)feature;

    // fill duplicated A tile (consumed after first __syncthreads below)
#pragma unroll
    for (int z = 0; z < (BM * D4) / 256; z++) {
        int idx = z * 256 + tid;
        int i   = idx >> 6;
        int k4  = idx & 63;
        float4 v = f4[(size_t)(n * Mm + i0 + i) * D4 + k4];
        float4* dst = (float4*)&As[(i * Dd + 4 * k4) * 2];
        dst[0] = make_float4(v.x, v.x, v.y, v.y);
        dst[1] = make_float4(v.z, v.z, v.w, v.w);
    }

    float si[8];
#pragma unroll
    for (int r = 0; r < 8; r++) si[r] = g_sq[n * Mm + i0 + it + 8 * r];

    float hp[8], hn[8], rsum[8];
#pragma unroll
    for (int r = 0; r < 8; r++) {
        hp[r] = 0.0f;
        hn[r] = __int_as_float(0x7f800000);
        rsum[r] = 0.0f;
    }

    unsigned long long acc[8][4];
#pragma unroll
    for (int r = 0; r < 8; r++)
#pragma unroll
        for (int p = 0; p < 4; p++) acc[r][p] = 0ull;

    float hardsum = 0.0f, distsum = 0.0f;

    for (int jp = 0; jp < 2; jp++) {
        const int j0 = jp * BN;
        const int rowbase = n * Mm + j0;

        float4 st[8];
#pragma unroll
        for (int q = 0; q < 8; q++) {
            int e = q * 256 + tid;
            st[q] = f4[(size_t)(rowbase + (e >> 3)) * D4 + (e & 7)];
        }

        for (int c = 0; c < NCHUNK; c++) {
            __syncthreads();   // prev compute done (also covers As fill)
#pragma unroll
            for (int q = 0; q < 8; q++) {
                int e = q * 256 + tid;
                int j = e >> 3, k4 = e & 7;
                float* b = &Bs[(4 * k4) * BSTR + j];
                b[0]        = st[q].x;
                b[BSTR]     = st[q].y;
                b[2 * BSTR] = st[q].z;
                b[3 * BSTR] = st[q].w;
            }
            __syncthreads();
            if (c + 1 < NCHUNK) {
                int kbase = (c + 1) * (BK / 4);
#pragma unroll
                for (int q = 0; q < 8; q++) {
                    int e = q * 256 + tid;
                    st[q] = f4[(size_t)(rowbase + (e >> 3)) * D4 + kbase + (e & 7)];
                }
            }
            const float* AsC = As + (c * BK) * 2;
#pragma unroll
            for (int kk = 0; kk < BK; kk += 2) {
                ulonglong2 a[8];
#pragma unroll
                for (int r = 0; r < 8; r++)
                    a[r] = *(const ulonglong2*)&AsC[((it + 8 * r) * Dd + kk) * 2];
                unsigned long long b0[4], b1[4];
#pragma unroll
                for (int p = 0; p < 4; p++) {
                    b0[p] = *(const unsigned long long*)&Bs[kk * BSTR + 2 * jt + 64 * p];
                    b1[p] = *(const unsigned long long*)&Bs[(kk + 1) * BSTR + 2 * jt + 64 * p];
                }
#pragma unroll
                for (int r = 0; r < 8; r++) {
#pragma unroll
                    for (int p = 0; p < 4; p++) {
                        fma2(acc[r][p], a[r].x, b0[p]);
                        fma2(acc[r][p], a[r].y, b1[p]);
                    }
                }
            }
        }

        // epilogue for this 256-col pass
#pragma unroll
        for (int p = 0; p < 4; p++) {
            int jg  = j0 + 2 * jt + 64 * p;
            float sj0 = g_sq[n * Mm + jg];
            float sj1 = g_sq[n * Mm + jg + 1];
            int jb0 = jg >> 3;
            int jb1 = (jg + 1) >> 3;
#pragma unroll
            for (int r = 0; r < 8; r++) {
                unsigned long long av = acc[r][p];
                acc[r][p] = 0ull;
                float g0 = __uint_as_float((unsigned)(av & 0xffffffffull));
                float g1 = __uint_as_float((unsigned)(av >> 32));
                int ib = (i0 + it + 8 * r) >> 3;
                float d0 = sqrtf(fmaxf(fmaf(-2.0f, g0, si[r] + sj0), 0.0f));
                float d1 = sqrtf(fmaxf(fmaf(-2.0f, g1, si[r] + sj1), 0.0f));
                rsum[r] += d0 + d1;
                if (ib == jb0) hp[r] = fmaxf(hp[r], d0); else hn[r] = fminf(hn[r], d0);
                if (ib == jb1) hp[r] = fmaxf(hp[r], d1); else hn[r] = fminf(hn[r], d1);
            }
        }
    }

    // warp reduce each of the 8 owned rows across 32 lanes
#pragma unroll
    for (int r = 0; r < 8; r++) {
        float h = hp[r], l = hn[r], s = rsum[r];
#pragma unroll
        for (int o = 16; o; o >>= 1) {
            h = fmaxf(h, __shfl_xor_sync(0xffffffffu, h, o));
            l = fminf(l, __shfl_xor_sync(0xffffffffu, l, o));
            s += __shfl_xor_sync(0xffffffffu, s, o);
        }
        hardsum += fmaxf(MARGIN_F + h - l, 0.0f);
        distsum += s;
    }

    // deterministic block combine (smem reused as scratch)
    __syncthreads();
    if (jt == 0) { As[it] = hardsum; As[16 + it] = distsum; }
    __syncthreads();
    if (tid == 0) {
        float h = 0.0f, d = 0.0f;
#pragma unroll
        for (int w = 0; w < 8; w++) { h += As[w]; d += As[16 + w]; }
        g_hard[n * (Mm / BM) + blockIdx.x] = h;
        g_dist[n * (Mm / BM) + blockIdx.x] = d;
    }
}

// ---------------- deterministic finalize ----------------
__global__ void finalize_kernel(float* __restrict__ out) {
    int t = threadIdx.x;
    if (t < Nn) {
        float s = 0.0f;
#pragma unroll
        for (int b = 0; b < (Mm / BM); b++) s += g_hard[t * (Mm / BM) + b];
        out[t] = s * (1.0f / (float)Mm);
    } else if (t >= 64 && t < 64 + Nn) {
        int nn = t - 64;
        float s = 0.0f;
#pragma unroll
        for (int b = 0; b < (Mm / BM); b++) s += g_dist[nn * (Mm / BM) + b];
        out[Nn + nn] = s * (1.0f / ((float)Mm * (float)Mm));
    }
}

extern "C" void kernel_launch(void* const* d_in, const int* in_sizes, int n_in,
                              void* d_out, int out_size) {
    (void)in_sizes; (void)n_in;
    const float* feature = (const float*)d_in[0];
    float* out = (float*)d_out;

    cudaMemsetAsync(d_out, 0, (size_t)out_size * sizeof(float), 0);

    sq_kernel<<<(Nn * Mm) / 8, 256>>>(feature);

    int smem_bytes = (BM * Dd * 2 + BK * BSTR) * (int)sizeof(float);
    static int attr_set = 0;
    if (!attr_set) {
        cudaFuncSetAttribute(triplet_kernel,
                             cudaFuncAttributeMaxDynamicSharedMemorySize,
                             smem_bytes);
        attr_set = 1;
    }
    dim3 grid(Mm / BM, Nn);
    triplet_kernel<<<grid, 256, smem_bytes>>>(feature);

    finalize_kernel<<<1, 128>>>(out);
}

// round 13
// speedup vs baseline: 1.0045x; 1.0045x over previous
#include <cuda_runtime.h>
#include <cstdint>

#define Nn 62
#define Mm 512
#define Dd 256
#define D4 (Dd / 4)
#define BM 64
#define BN 256
#define BK 32
#define BSTR 258
#define NCHUNK (Dd / BK)
#define MARGIN_F 0.2f

__device__ float g_sq[Nn * Mm];
__device__ float g_hard[Nn * (Mm / BM)];
__device__ float g_dist[Nn * (Mm / BM)];

__device__ __forceinline__ void fma2(unsigned long long& c,
                                     unsigned long long a,
                                     unsigned long long b) {
    asm("fma.rn.f32x2 %0, %1, %2, %0;" : "+l"(c) : "l"(a), "l"(b));
}

// ---------------- squared row norms: one warp per row ----------------
__global__ void sq_kernel(const float* __restrict__ f) {
    int row  = blockIdx.x * 8 + (threadIdx.x >> 5);
    int lane = threadIdx.x & 31;
    const float4* f4 = (const float4*)f + (size_t)row * D4;
    float4 v0 = f4[lane];
    float4 v1 = f4[lane + 32];
    float s = v0.x * v0.x + v0.y * v0.y + v0.z * v0.z + v0.w * v0.w
            + v1.x * v1.x + v1.y * v1.y + v1.z * v1.z + v1.w * v1.w;
#pragma unroll
    for (int o = 16; o; o >>= 1) s += __shfl_xor_sync(0xffffffffu, s, o);
    if (lane == 0) g_sq[row] = s;
}

// ---- main: gram GEMM (f32x2) + dist + hard pos/neg per 64-row tile ----
__global__ void __launch_bounds__(256, 1)
triplet_kernel(const float* __restrict__ feature) {
    extern __shared__ float smem[];
    float* As = smem;                  // BM*Dd*2 floats, duplicated {a,a}
    float* Bs = smem + BM * Dd * 2;    // BK*BSTR floats, transposed [k][j]

    const int tid = threadIdx.x;
    const int it  = tid >> 5;          // warp id: rows it+8r
    const int jt  = tid & 31;          // lane: cols 2*jt+64p (+0/1)
    const int n   = blockIdx.y;
    const int i0  = blockIdx.x * BM;
    const float4* f4 = (const float4*)feature;

    // fill duplicated A tile (consumed after first __syncthreads below)
#pragma unroll
    for (int z = 0; z < (BM * D4) / 256; z++) {
        int idx = z * 256 + tid;
        int i   = idx >> 6;
        int k4  = idx & 63;
        float4 v = f4[(size_t)(n * Mm + i0 + i) * D4 + k4];
        float4* dst = (float4*)&As[(i * Dd + 4 * k4) * 2];
        dst[0] = make_float4(v.x, v.x, v.y, v.y);
        dst[1] = make_float4(v.z, v.z, v.w, v.w);
    }

    float si[8];
#pragma unroll
    for (int r = 0; r < 8; r++) si[r] = g_sq[n * Mm + i0 + it + 8 * r];

    float hp[8], hn[8], rsum[8];
#pragma unroll
    for (int r = 0; r < 8; r++) {
        hp[r] = 0.0f;
        hn[r] = __int_as_float(0x7f800000);
        rsum[r] = 0.0f;
    }

    unsigned long long acc[8][4];
#pragma unroll
    for (int r = 0; r < 8; r++)
#pragma unroll
        for (int p = 0; p < 4; p++) acc[r][p] = 0ull;

    float hardsum = 0.0f, distsum = 0.0f;

    for (int jp = 0; jp < 2; jp++) {
        const int j0 = jp * BN;
        const int rowbase = n * Mm + j0;

        float4 st[8];
#pragma unroll
        for (int q = 0; q < 8; q++) {
            int e = q * 256 + tid;
            st[q] = f4[(size_t)(rowbase + (e >> 3)) * D4 + (e & 7)];
        }

        for (int c = 0; c < NCHUNK; c++) {
            __syncthreads();   // prev compute done (also covers As fill)
#pragma unroll
            for (int q = 0; q < 8; q++) {
                int e = q * 256 + tid;
                int j = e >> 3, k4 = e & 7;
                float* b = &Bs[(4 * k4) * BSTR + j];
                b[0]        = st[q].x;
                b[BSTR]     = st[q].y;
                b[2 * BSTR] = st[q].z;
                b[3 * BSTR] = st[q].w;
            }
            __syncthreads();
            if (c + 1 < NCHUNK) {
                int kbase = (c + 1) * (BK / 4);
#pragma unroll
                for (int q = 0; q < 8; q++) {
                    int e = q * 256 + tid;
                    st[q] = f4[(size_t)(rowbase + (e >> 3)) * D4 + kbase + (e & 7)];
                }
            }
            const float* AsC = As + (c * BK) * 2;
#pragma unroll
            for (int kk = 0; kk < BK; kk += 2) {
                ulonglong2 a[8];
#pragma unroll
                for (int r = 0; r < 8; r++)
                    a[r] = *(const ulonglong2*)&AsC[((it + 8 * r) * Dd + kk) * 2];
                unsigned long long b0[4], b1[4];
#pragma unroll
                for (int p = 0; p < 4; p++) {
                    b0[p] = *(const unsigned long long*)&Bs[kk * BSTR + 2 * jt + 64 * p];
                    b1[p] = *(const unsigned long long*)&Bs[(kk + 1) * BSTR + 2 * jt + 64 * p];
                }
#pragma unroll
                for (int r = 0; r < 8; r++) {
#pragma unroll
                    for (int p = 0; p < 4; p++) {
                        fma2(acc[r][p], a[r].x, b0[p]);
                        fma2(acc[r][p], a[r].y, b1[p]);
                    }
                }
            }
        }

        // epilogue for this 256-col pass
#pragma unroll
        for (int p = 0; p < 4; p++) {
            int jg  = j0 + 2 * jt + 64 * p;
            float sj0 = g_sq[n * Mm + jg];
            float sj1 = g_sq[n * Mm + jg + 1];
            int jb0 = jg >> 3;
            int jb1 = (jg + 1) >> 3;
#pragma unroll
            for (int r = 0; r < 8; r++) {
                unsigned long long av = acc[r][p];
                acc[r][p] = 0ull;
                float g0 = __uint_as_float((unsigned)(av & 0xffffffffull));
                float g1 = __uint_as_float((unsigned)(av >> 32));
                int ib = (i0 + it + 8 * r) >> 3;
                float d0 = sqrtf(fmaxf(fmaf(-2.0f, g0, si[r] + sj0), 0.0f));
                float d1 = sqrtf(fmaxf(fmaf(-2.0f, g1, si[r] + sj1), 0.0f));
                rsum[r] += d0 + d1;
                if (ib == jb0) hp[r] = fmaxf(hp[r], d0); else hn[r] = fminf(hn[r], d0);
                if (ib == jb1) hp[r] = fmaxf(hp[r], d1); else hn[r] = fminf(hn[r], d1);
            }
        }
    }

    // warp reduce each of the 8 owned rows across 32 lanes
#pragma unroll
    for (int r = 0; r < 8; r++) {
        float h = hp[r], l = hn[r], s = rsum[r];
#pragma unroll
        for (int o = 16; o; o >>= 1) {
            h = fmaxf(h, __shfl_xor_sync(0xffffffffu, h, o));
            l = fminf(l, __shfl_xor_sync(0xffffffffu, l, o));
            s += __shfl_xor_sync(0xffffffffu, s, o);
        }
        hardsum += fmaxf(MARGIN_F + h - l, 0.0f);
        distsum += s;
    }

    // deterministic block combine (smem reused as scratch)
    __syncthreads();
    if (jt == 0) { As[it] = hardsum; As[16 + it] = distsum; }
    __syncthreads();
    if (tid == 0) {
        float h = 0.0f, d = 0.0f;
#pragma unroll
        for (int w = 0; w < 8; w++) { h += As[w]; d += As[16 + w]; }
        g_hard[n * (Mm / BM) + blockIdx.x] = h;
        g_dist[n * (Mm / BM) + blockIdx.x] = d;
    }
}

// ---------------- deterministic finalize ----------------
__global__ void finalize_kernel(float* __restrict__ out) {
    int t = threadIdx.x;
    if (t < Nn) {
        float s = 0.0f;
#pragma unroll
        for (int b = 0; b < (Mm / BM); b++) s += g_hard[t * (Mm / BM) + b];
        out[t] = s * (1.0f / (float)Mm);
    } else if (t >= 64 && t < 64 + Nn) {
        int nn = t - 64;
        float s = 0.0f;
#pragma unroll
        for (int b = 0; b < (Mm / BM); b++) s += g_dist[nn * (Mm / BM) + b];
        out[Nn + nn] = s * (1.0f / ((float)Mm * (float)Mm));
    }
}

extern "C" void kernel_launch(void* const* d_in, const int* in_sizes, int n_in,
                              void* d_out, int out_size) {
    (void)in_sizes; (void)n_in;
    const float* feature = (const float*)d_in[0];
    float* out = (float*)d_out;

    cudaMemsetAsync(d_out, 0, (size_t)out_size * sizeof(float), 0);

    sq_kernel<<<(Nn * Mm) / 8, 256>>>(feature);

    int smem_bytes = (BM * Dd * 2 + BK * BSTR) * (int)sizeof(float);
    static int attr_set = 0;
    if (!attr_set) {
        cudaFuncSetAttribute(triplet_kernel,
                             cudaFuncAttributeMaxDynamicSharedMemorySize,
                             smem_bytes);
        attr_set = 1;
    }
    dim3 grid(Mm / BM, Nn);
    triplet_kernel<<<grid, 256, smem_bytes>>>(feature);

    finalize_kernel<<<1, 128>>>(out);
}

// round 14
// speedup vs baseline: 1.0067x; 1.0021x over previous
#include <cuda_runtime.h>
#include <cstdint>

#define Nn 62
#define Mm 512
#define Dd 256
#define D4 (Dd / 4)
#define BM 64
#define BN 256
#define BK 32
#define BSTR 258
#define NCHUNK (Dd / BK)
#define MARGIN_F 0.2f

__device__ float g_sq[Nn * Mm];
__device__ float g_hard[Nn * (Mm / BM)];
__device__ float g_dist[Nn * (Mm / BM)];

__device__ __forceinline__ void fma2(unsigned long long& c,
                                     unsigned long long a,
                                     unsigned long long b) {
    asm("fma.rn.f32x2 %0, %1, %2, %0;" : "+l"(c) : "l"(a), "l"(b));
}

// ---------------- squared row norms: one warp per row ----------------
__global__ void sq_kernel(const float* __restrict__ f) {
    int row  = blockIdx.x * 8 + (threadIdx.x >> 5);
    int lane = threadIdx.x & 31;
    const float4* f4 = (const float4*)f + (size_t)row * D4;
    float4 v0 = f4[lane];
    float4 v1 = f4[lane + 32];
    float s = v0.x * v0.x + v0.y * v0.y + v0.z * v0.z + v0.w * v0.w
            + v1.x * v1.x + v1.y * v1.y + v1.z * v1.z + v1.w * v1.w;
#pragma unroll
    for (int o = 16; o; o >>= 1) s += __shfl_xor_sync(0xffffffffu, s, o);
    if (lane == 0) g_sq[row] = s;
}

// ---- main: gram GEMM (f32x2) + dist + hard pos/neg per 64-row tile ----
__global__ void __launch_bounds__(256, 1)
triplet_kernel(const float* __restrict__ feature) {
    extern __shared__ float smem[];
    float* As = smem;                  // BM*Dd*2 floats, duplicated {a,a}
    float* Bs = smem + BM * Dd * 2;    // BK*BSTR floats, transposed [k][j]

    const int tid = threadIdx.x;
    const int it  = tid >> 5;          // warp id: rows it+8r
    const int jt  = tid & 31;          // lane: cols 2*jt+64p (+0/1)
    const int n   = blockIdx.y;
    const int i0  = blockIdx.x * BM;
    const float4* f4 = (const float4*)feature;

    // fill duplicated A tile (consumed after first __syncthreads below)
#pragma unroll
    for (int z = 0; z < (BM * D4) / 256; z++) {
        int idx = z * 256 + tid;
        int i   = idx >> 6;
        int k4  = idx & 63;
        float4 v = f4[(size_t)(n * Mm + i0 + i) * D4 + k4];
        float4* dst = (float4*)&As[(i * Dd + 4 * k4) * 2];
        dst[0] = make_float4(v.x, v.x, v.y, v.y);
        dst[1] = make_float4(v.z, v.z, v.w, v.w);
    }

    float si[8];
#pragma unroll
    for (int r = 0; r < 8; r++) si[r] = g_sq[n * Mm + i0 + it + 8 * r];

    float hp[8], hn[8], rsum[8];
#pragma unroll
    for (int r = 0; r < 8; r++) {
        hp[r] = 0.0f;
        hn[r] = __int_as_float(0x7f800000);
        rsum[r] = 0.0f;
    }

    unsigned long long acc[8][4];
#pragma unroll
    for (int r = 0; r < 8; r++)
#pragma unroll
        for (int p = 0; p < 4; p++) acc[r][p] = 0ull;

    float hardsum = 0.0f, distsum = 0.0f;

    for (int jp = 0; jp < 2; jp++) {
        const int j0 = jp * BN;
        const int rowbase = n * Mm + j0;

        float4 st[8];
#pragma unroll
        for (int q = 0; q < 8; q++) {
            int e = q * 256 + tid;
            st[q] = f4[(size_t)(rowbase + (e >> 3)) * D4 + (e & 7)];
        }

        for (int c = 0; c < NCHUNK; c++) {
            __syncthreads();   // prev compute done (also covers As fill)
#pragma unroll
            for (int q = 0; q < 8; q++) {
                int e = q * 256 + tid;
                int j = e >> 3, k4 = e & 7;
                float* b = &Bs[(4 * k4) * BSTR + j];
                b[0]        = st[q].x;
                b[BSTR]     = st[q].y;
                b[2 * BSTR] = st[q].z;
                b[3 * BSTR] = st[q].w;
            }
            __syncthreads();
            if (c + 1 < NCHUNK) {
                int kbase = (c + 1) * (BK / 4);
#pragma unroll
                for (int q = 0; q < 8; q++) {
                    int e = q * 256 + tid;
                    st[q] = f4[(size_t)(rowbase + (e >> 3)) * D4 + kbase + (e & 7)];
                }
            }
            const float* AsC = As + (c * BK) * 2;
#pragma unroll
            for (int kk = 0; kk < BK; kk += 2) {
                ulonglong2 a[8];
#pragma unroll
                for (int r = 0; r < 8; r++)
                    a[r] = *(const ulonglong2*)&AsC[((it + 8 * r) * Dd + kk) * 2];
                unsigned long long b0[4], b1[4];
#pragma unroll
                for (int p = 0; p < 4; p++) {
                    b0[p] = *(const unsigned long long*)&Bs[kk * BSTR + 2 * jt + 64 * p];
                    b1[p] = *(const unsigned long long*)&Bs[(kk + 1) * BSTR + 2 * jt + 64 * p];
                }
#pragma unroll
                for (int r = 0; r < 8; r++) {
#pragma unroll
                    for (int p = 0; p < 4; p++) {
                        fma2(acc[r][p], a[r].x, b0[p]);
                        fma2(acc[r][p], a[r].y, b1[p]);
                    }
                }
            }
        }

        // epilogue for this 256-col pass
#pragma unroll
        for (int p = 0; p < 4; p++) {
            int jg  = j0 + 2 * jt + 64 * p;
            float sj0 = g_sq[n * Mm + jg];
            float sj1 = g_sq[n * Mm + jg + 1];
            int jb0 = jg >> 3;
            int jb1 = (jg + 1) >> 3;
#pragma unroll
            for (int r = 0; r < 8; r++) {
                unsigned long long av = acc[r][p];
                acc[r][p] = 0ull;
                float g0 = __uint_as_float((unsigned)(av & 0xffffffffull));
                float g1 = __uint_as_float((unsigned)(av >> 32));
                int ib = (i0 + it + 8 * r) >> 3;
                float d0 = sqrtf(fmaxf(fmaf(-2.0f, g0, si[r] + sj0), 0.0f));
                float d1 = sqrtf(fmaxf(fmaf(-2.0f, g1, si[r] + sj1), 0.0f));
                rsum[r] += d0 + d1;
                if (ib == jb0) hp[r] = fmaxf(hp[r], d0); else hn[r] = fminf(hn[r], d0);
                if (ib == jb1) hp[r] = fmaxf(hp[r], d1); else hn[r] = fminf(hn[r], d1);
            }
        }
    }

    // warp reduce each of the 8 owned rows across 32 lanes
#pragma unroll
    for (int r = 0; r < 8; r++) {
        float h = hp[r], l = hn[r], s = rsum[r];
#pragma unroll
        for (int o = 16; o; o >>= 1) {
            h = fmaxf(h, __shfl_xor_sync(0xffffffffu, h, o));
            l = fminf(l, __shfl_xor_sync(0xffffffffu, l, o));
            s += __shfl_xor_sync(0xffffffffu, s, o);
        }
        hardsum += fmaxf(MARGIN_F + h - l, 0.0f);
        distsum += s;
    }

    // deterministic block combine (smem reused as scratch)
    __syncthreads();
    if (jt == 0) { As[it] = hardsum; As[16 + it] = distsum; }
    __syncthreads();
    if (tid == 0) {
        float h = 0.0f, d = 0.0f;
#pragma unroll
        for (int w = 0; w < 8; w++) { h += As[w]; d += As[16 + w]; }
        g_hard[n * (Mm / BM) + blockIdx.x] = h;
        g_dist[n * (Mm / BM) + blockIdx.x] = d;
    }
}

// ---------------- deterministic finalize ----------------
__global__ void finalize_kernel(float* __restrict__ out) {
    int t = threadIdx.x;
    if (t < Nn) {
        float s = 0.0f;
#pragma unroll
        for (int b = 0; b < (Mm / BM); b++) s += g_hard[t * (Mm / BM) + b];
        out[t] = s * (1.0f / (float)Mm);
    } else if (t >= 64 && t < 64 + Nn) {
        int nn = t - 64;
        float s = 0.0f;
#pragma unroll
        for (int b = 0; b < (Mm / BM); b++) s += g_dist[nn * (Mm / BM) + b];
        out[Nn + nn] = s * (1.0f / ((float)Mm * (float)Mm));
    }
}

extern "C" void kernel_launch(void* const* d_in, const int* in_sizes, int n_in,
                              void* d_out, int out_size) {
    (void)in_sizes; (void)n_in;
    const float* feature = (const float*)d_in[0];
    float* out = (float*)d_out;

    cudaMemsetAsync(d_out, 0, (size_t)out_size * sizeof(float), 0);

    sq_kernel<<<(Nn * Mm) / 8, 256>>>(feature);

    int smem_bytes = (BM * Dd * 2 + BK * BSTR) * (int)sizeof(float);
    static int attr_set = 0;
    if (!attr_set) {
        cudaFuncSetAttribute(triplet_kernel,
                             cudaFuncAttributeMaxDynamicSharedMemorySize,
                             smem_bytes);
        attr_set = 1;
    }
    dim3 grid(Mm / BM, Nn);
    triplet_kernel<<<grid, 256, smem_bytes>>>(feature);

    finalize_kernel<<<1, 128>>>(out);
}